// round 1
// baseline (speedup 1.0000x reference)
#include <cuda_runtime.h>
#include <cstdint>
#include <cstddef>

// Problem constants
#define B_BATCH 512
#define F_DIM   64
#define D_DIM   32
#define O_DIM   128

// Scratch for inter-layer activations (allocation-free rule -> __device__ globals)
__device__ float g_x1[B_BATCH * O_DIM * D_DIM];  // 8 MB
__device__ float g_x2[B_BATCH * O_DIM * D_DIM];  // 8 MB

// ---------------------------------------------------------------------------
// One layer:
//   pre[b,o,d] = sum_{h,f} W[o, h*64+f] * x[b,h,d] * inp[b,f,d] + bias[o]
//   act = relu(pre)
//   if WRITE_NEXT: x_next[b,o,d] = act
//   out[b, out_off+o] = sum_d act
//
// Block: 2 batches, full O=128 x 64 columns (2 batches x 32 d).
// 128 threads, each owns an 8(o) x 8(col) register tile, accumulated as
// f32x2 pairs via fma.rn.f32x2 (2x fp32 FMA throughput vs 3-reg FFMA on
// Blackwell). Z = x*inp is generated per-K-tile into smem; W tile is staged
// transposed in smem so both operands stream as LDS.128.
// ---------------------------------------------------------------------------
template <int H, bool WRITE_NEXT>
__global__ __launch_bounds__(128)
void layer_kernel(const float* __restrict__ x,      // [B, H, 32]
                  const float* __restrict__ inp,    // [B, 64, 32]
                  const float* __restrict__ W,      // [128, H*64]
                  const float* __restrict__ bias,   // [128]
                  float* __restrict__ x_next,       // [B, 128, 32] (or unused)
                  float* __restrict__ out,          // [B, 384]
                  int out_off)
{
    constexpr int K  = H * 64;
    constexpr int KT = 32;

    __shared__ __align__(16) float inp_s[2 * 64 * 32];  // 16 KB (both batches)
    __shared__ __align__(16) float wt_s[KT][128];       // 16 KB (transposed W tile)
    __shared__ __align__(16) float z_s[KT][64];         //  8 KB (Z tile)
    __shared__ float red_s[2][128];                     //  1 KB (per-o sums)

    const int tid    = threadIdx.x;
    const int b0     = blockIdx.x * 2;
    const int o_base = (tid >> 3) * 8;   // 16 o-groups
    const int c_base = (tid & 7) * 8;    //  8 col-groups (8 cols each, same batch)
    const int bl     = c_base >> 5;      // which of the 2 batches
    const int d0     = c_base & 31;      // first d of this thread's columns

    // Stage input for both batches into smem (reused across the whole K loop)
    {
        const float4* src = (const float4*)(inp + (size_t)b0 * 64 * 32);
        float4*       dst = (float4*)inp_s;
#pragma unroll
        for (int i = 0; i < 8; i++) dst[tid + i * 128] = src[tid + i * 128];
    }
    red_s[0][tid] = 0.0f;
    red_s[1][tid] = 0.0f;

    // 8x8 accumulator tile as 8x4 packed f32x2 (zero bits == {0.f, 0.f})
    unsigned long long acc[8][4];
#pragma unroll
    for (int i = 0; i < 8; i++)
#pragma unroll
        for (int j = 0; j < 4; j++) acc[i][j] = 0ull;

    const float* xb = x + (size_t)b0 * H * 32;

    for (int k0 = 0; k0 < K; k0 += KT) {
        __syncthreads();  // protect smem tiles from previous iteration's readers

        // --- Stage W tile transposed: wt_s[kt][o].  Thread tid owns row o=tid.
        {
            const float4* wrow = (const float4*)(W + (size_t)tid * K + k0);
#pragma unroll
            for (int j = 0; j < 8; j++) {
                float4 v = wrow[j];
                wt_s[j * 4 + 0][tid] = v.x;
                wt_s[j * 4 + 1][tid] = v.y;
                wt_s[j * 4 + 2][tid] = v.z;
                wt_s[j * 4 + 3][tid] = v.w;
            }
        }
        // --- Generate Z tile: z[kt][c] = x[b,h,d] * inp[b,f,d]
        // Tile spans one h (KT=32 <= 64, k0 is 32-aligned) and 32 consecutive f.
        {
            const int h     = k0 >> 6;
            const int fbase = k0 & 63;
#pragma unroll
            for (int i = 0; i < 16; i++) {
                int idx = tid + i * 128;       // 0..2047
                int kt  = idx >> 6;            // 0..31
                int c   = idx & 63;
                int blz = c >> 5;
                int d   = c & 31;
                float xv = xb[(blz * H + h) * 32 + d];     // L1-resident (64 vals/tile)
                z_s[kt][c] = xv * inp_s[blz * 2048 + (fbase + kt) * 32 + d];
            }
        }
        __syncthreads();

        // --- Main MAC loop: per kt: 4x LDS.128, 8x mov.b64 dup, 32x fma.rn.f32x2
#pragma unroll
        for (int kt = 0; kt < KT; kt++) {
            ulonglong2 zt0 = *(const ulonglong2*)&z_s[kt][c_base];
            ulonglong2 zt1 = *(const ulonglong2*)&z_s[kt][c_base + 4];
            unsigned long long zp[4] = {zt0.x, zt0.y, zt1.x, zt1.y};

            float4 w0 = *(const float4*)&wt_s[kt][o_base];
            float4 w1 = *(const float4*)&wt_s[kt][o_base + 4];
            float wv[8] = {w0.x, w0.y, w0.z, w0.w, w1.x, w1.y, w1.z, w1.w};

            unsigned long long wd[8];
#pragma unroll
            for (int j = 0; j < 8; j++)
                asm("mov.b64 %0, {%1, %1};" : "=l"(wd[j]) : "f"(wv[j]));

#pragma unroll
            for (int oi = 0; oi < 8; oi++)
#pragma unroll
                for (int cp = 0; cp < 4; cp++)
                    asm("fma.rn.f32x2 %0, %1, %2, %0;"
                        : "+l"(acc[oi][cp])
                        : "l"(wd[oi]), "l"(zp[cp]));
        }
    }

    // --- Epilogue: bias, relu, write x_next, reduce over d into out
    const int b = b0 + bl;
#pragma unroll
    for (int oi = 0; oi < 8; oi++) {
        const int o = o_base + oi;
        const float bv = __ldg(&bias[o]);
        float vals[8];
        float psum = 0.0f;
#pragma unroll
        for (int cp = 0; cp < 4; cp++) {
            float v0, v1;
            asm("mov.b64 {%0, %1}, %2;" : "=f"(v0), "=f"(v1) : "l"(acc[oi][cp]));
            v0 = fmaxf(v0 + bv, 0.0f);
            v1 = fmaxf(v1 + bv, 0.0f);
            vals[cp * 2]     = v0;
            vals[cp * 2 + 1] = v1;
            psum += v0 + v1;
        }
        if (WRITE_NEXT) {
            float* dst = x_next + ((size_t)b * 128 + o) * 32 + d0;
            *(float4*)(dst)     = make_float4(vals[0], vals[1], vals[2], vals[3]);
            *(float4*)(dst + 4) = make_float4(vals[4], vals[5], vals[6], vals[7]);
        }
        atomicAdd(&red_s[bl][o], psum);
    }
    __syncthreads();

#pragma unroll
    for (int r = 0; r < 2; r++)
        out[(size_t)(b0 + r) * 384 + out_off + tid] = red_s[r][tid];
}

// ---------------------------------------------------------------------------
// Inputs (metadata order): input[512,64,32], W0[128,4096], b0[128],
//                          W1[128,8192], b1[128], W2[128,8192], b2[128]
// Output: [512, 384] float32
// ---------------------------------------------------------------------------
extern "C" void kernel_launch(void* const* d_in, const int* in_sizes, int n_in,
                              void* d_out, int out_size)
{
    (void)in_sizes; (void)n_in; (void)out_size;
    const float* input = (const float*)d_in[0];
    const float* W0    = (const float*)d_in[1];
    const float* b0    = (const float*)d_in[2];
    const float* W1    = (const float*)d_in[3];
    const float* b1    = (const float*)d_in[4];
    const float* W2    = (const float*)d_in[5];
    const float* b2    = (const float*)d_in[6];
    float* out = (float*)d_out;

    float *x1 = nullptr, *x2 = nullptr;
    cudaGetSymbolAddress((void**)&x1, g_x1);
    cudaGetSymbolAddress((void**)&x2, g_x2);

    dim3 grid(B_BATCH / 2);
    dim3 block(128);

    layer_kernel<64,  true ><<<grid, block>>>(input, input, W0, b0, x1, out, 0);
    layer_kernel<128, true ><<<grid, block>>>(x1,    input, W1, b1, x2, out, 128);
    layer_kernel<128, false><<<grid, block>>>(x2,    input, W2, b2, nullptr, out, 256);
}

// round 4
// speedup vs baseline: 3.4286x; 3.4286x over previous
#include <cuda_runtime.h>
#include <cuda_bf16.h>
#include <cstdint>
#include <cstddef>

// ---------------------------------------------------------------------------
// pre[b,o,d] = sum_{h,f} W[o, h*64+f] * x[b,h,d] * inp[b,f,d] + bias[o]
// x_next = relu(pre);  out[:, off+o] = sum_d relu(pre);  3 chained layers.
// B=512, F=64, D=32, O=128.
//
// GEMM per layer: D[o=128, n=(b*32+d)=16384] = W[o,k] * Z[k,n],
// Z[h*64+f, (b,d)] = x[b,h,d]*inp[b,f,d] generated on the fly in SMEM.
// Tensor path: mma.sync.aligned.m16n8k16 bf16 (compute_100-safe; tcgen05 is
// not available in this harness's PTX target).
// Accuracy: 3-MMA bf16 split (Whi*Zhi + Whi*Zlo + Wlo*Zhi).
// W pre-split once into swizzled bf16 tiles (prep kernel) -> cp.async stream.
// CTA: M=128 (all o), N=128 (4 batches), K-tile 64 (== one h), double buffer.
//
// Swizzle note: SW128(row*128+col) == row*128 + (col ^ ((row&7)<<4)) for
// col<128. All in-loop addressing uses linear col advance + constant XOR mask
// applied AFTER the add (adding after XOR carries into the row bits -> the
// round-3 OOB).
// ---------------------------------------------------------------------------

#define SW128(o) ((o) ^ (((o) >> 3) & 0x70))

__device__ __align__(16) float g_x1[512 * 128 * 32];
__device__ __align__(16) float g_x2[512 * 128 * 32];
// Pre-split W, tile layout: per 64-k tile: [Whi 16KB][Wlo 16KB], rows swizzled
__device__ uint4 g_W0[128 * 4096 * 4 / 16];
__device__ uint4 g_W1[128 * 8192 * 4 / 16];
__device__ uint4 g_W2[128 * 8192 * 4 / 16];

__device__ __forceinline__ uint32_t smem_u32(const void* p) {
    uint32_t a;
    asm("{ .reg .u64 t; cvta.to.shared.u64 t, %1; cvt.u32.u64 %0, t; }"
        : "=r"(a) : "l"(p));
    return a;
}

// Split (z0, z1) into packed bf16x2 hi and lo (z ~= hi + lo)
__device__ __forceinline__ void split2(float z0, float z1,
                                       uint32_t& hi, uint32_t& lo) {
    __nv_bfloat162 h = __floats2bfloat162_rn(z0, z1);
    float2 hf = __bfloat1622float2(h);
    __nv_bfloat162 l = __floats2bfloat162_rn(z0 - hf.x, z1 - hf.y);
    hi = reinterpret_cast<uint32_t&>(h);
    lo = reinterpret_cast<uint32_t&>(l);
}

__device__ __forceinline__ void ldsm4(uint32_t r[4], uint32_t addr) {
    asm volatile("ldmatrix.sync.aligned.m8n8.x4.shared.b16 {%0,%1,%2,%3}, [%4];"
                 : "=r"(r[0]), "=r"(r[1]), "=r"(r[2]), "=r"(r[3]) : "r"(addr));
}

__device__ __forceinline__ void mma_bf16(float c[4], const uint32_t a[4],
                                         uint32_t b0, uint32_t b1) {
    asm volatile(
        "mma.sync.aligned.m16n8k16.row.col.f32.bf16.bf16.f32 "
        "{%0,%1,%2,%3}, {%4,%5,%6,%7}, {%8,%9}, {%0,%1,%2,%3};"
        : "+f"(c[0]), "+f"(c[1]), "+f"(c[2]), "+f"(c[3])
        : "r"(a[0]), "r"(a[1]), "r"(a[2]), "r"(a[3]), "r"(b0), "r"(b1));
}

// --------------------------- W prep: fp32 -> split bf16 tiles ---------------
__global__ __launch_bounds__(256)
void prep_w(const float* __restrict__ W, uint4* __restrict__ dst, int K) {
    int idx = blockIdx.x * 256 + threadIdx.x;       // one 8-elem k-chunk
    int cpr = K >> 3;
    if (idx >= 128 * cpr) return;
    int o = idx / cpr;
    int k = (idx % cpr) * 8;
    const float4* src = (const float4*)(W + (size_t)o * K + k);
    float4 v0 = src[0], v1 = src[1];
    float zf[8] = {v0.x, v0.y, v0.z, v0.w, v1.x, v1.y, v1.z, v1.w};
    uint32_t hi[4], lo[4];
#pragma unroll
    for (int p = 0; p < 4; p++) split2(zf[2 * p], zf[2 * p + 1], hi[p], lo[p]);
    char* base = (char*)dst + (size_t)(k >> 6) * 32768;
    uint32_t off = SW128((uint32_t)(o * 128 + (k & 63) * 2));  // single access: full swizzle ok
    *(uint4*)(base + off)         = make_uint4(hi[0], hi[1], hi[2], hi[3]);
    *(uint4*)(base + 16384 + off) = make_uint4(lo[0], lo[1], lo[2], lo[3]);
}

// --------------------------- main layer kernel ------------------------------
// SMEM: [0,32768)   inp_s (4 batches x 64 f x 32 d fp32)
//       [32768 + s*65536): stage s = Whi(16K) Wlo(16K) Zhi(16K) Zlo(16K)
#define SMEM_TOTAL 163840
#define STAGE_OFF  32768

template <int H, bool WRITE_NEXT>
__global__ __launch_bounds__(256, 1)
void layer_mma(const float* __restrict__ x,      // [B, H, 32]
               const float* __restrict__ inp,    // [B, 64, 32]
               const uint4* __restrict__ Wsp,    // pre-split tiles
               const float* __restrict__ bias,   // [128]
               float* __restrict__ x_next,       // [B, 128, 32]
               float* __restrict__ out,          // [B, 384]
               int out_off)
{
    extern __shared__ char smem[];
    const uint32_t sb = smem_u32(smem);
    float* inp_s = (float*)smem;
    const int tid  = threadIdx.x;
    const int lane = tid & 31;
    const int w    = tid >> 5;
    const int wm   = w & 3;     // m block (32 rows)
    const int wn   = w >> 2;    // n block (64 cols)
    const int b0   = blockIdx.x * 4;

    // Stage inp for the CTA's 4 batches
    {
        const float4* src = (const float4*)(inp + (size_t)b0 * 2048);
        float4* dst = (float4*)inp_s;
#pragma unroll
        for (int i = 0; i < 8; i++) dst[tid + i * 256] = src[tid + i * 256];
    }

    // Producer-side constants: thread -> (n, k-half)
    const int n  = tid & 127;
    const int bq = n >> 5;
    const int dd = n & 31;
    const int kh = (tid >> 7) * 32;
    const float* xp = x + ((size_t)(b0 + bq) * H) * 32 + dd;   // + h*32 per tile
    const float* ip = inp_s + (size_t)bq * 2048 + kh * 32 + dd;
    const uint32_t zrow  = (uint32_t)n * 128;
    const uint32_t zmask = (uint32_t)((n & 7) << 4);
    const uint32_t zcol0 = (uint32_t)(kh * 2);

    // MMA-side constants: linear row bases + per-kk swizzled column offsets.
    // Row mask reduces to (lane&7)<<4 for every ldmatrix address here.
    const int g = lane >> 3;
    const uint32_t maskL = (uint32_t)((lane & 7) << 4);
    uint32_t aRow[2], bRow[4], aCol[4], bCol[4];
#pragma unroll
    for (int mi = 0; mi < 2; mi++)
        aRow[mi] = (uint32_t)((32 * wm + 16 * mi + (lane & 7) + (g & 1) * 8) * 128);
#pragma unroll
    for (int p = 0; p < 4; p++)
        bRow[p] = (uint32_t)((64 * wn + 16 * p + 8 * ((g >> 1) & 1) + (lane & 7)) * 128);
#pragma unroll
    for (int kk = 0; kk < 4; kk++) {
        aCol[kk] = ((uint32_t)(((g >> 1) & 1) * 16 + 32 * kk)) ^ maskL;
        bCol[kk] = ((uint32_t)((g & 1) * 16 + 32 * kk)) ^ maskL;
    }

    float C[2][8][4];
#pragma unroll
    for (int i = 0; i < 2; i++)
#pragma unroll
        for (int j = 0; j < 8; j++)
#pragma unroll
            for (int q = 0; q < 4; q++) C[i][j][q] = 0.f;

    const char* gW = (const char*)Wsp;

    // Z producer for tile h into stage s
    auto prodZ = [&](int h, int s) {
        char* zp = smem + STAGE_OFF + s * 65536 + 32768;  // Zhi
        const float xv = __ldg(xp + h * 32);
#pragma unroll
        for (int i = 0; i < 4; i++) {
            float z[8];
#pragma unroll
            for (int j = 0; j < 8; j++) z[j] = xv * ip[(i * 8 + j) * 32];
            uint32_t hi[4], lo[4];
#pragma unroll
            for (int p = 0; p < 4; p++)
                split2(z[2 * p], z[2 * p + 1], hi[p], lo[p]);
            uint32_t off = zrow + ((zcol0 + 16u * i) ^ zmask);   // swizzle AFTER add
            *(uint4*)(zp + off)         = make_uint4(hi[0], hi[1], hi[2], hi[3]);
            *(uint4*)(zp + 16384 + off) = make_uint4(lo[0], lo[1], lo[2], lo[3]);
        }
    };
    // W tile copy via cp.async (layout already matches SMEM)
    auto copyW = [&](int it, int s) {
        uint32_t dsb = sb + STAGE_OFF + s * 65536 + tid * 16;
        const char* srcW = gW + (size_t)it * 32768 + tid * 16;
#pragma unroll
        for (int i = 0; i < 8; i++)
            asm volatile("cp.async.cg.shared.global [%0], [%1], 16;"
                         :: "r"(dsb + i * 4096), "l"(srcW + i * 4096));
        asm volatile("cp.async.commit_group;");
    };

    __syncthreads();   // inp_s ready

    // Prologue: stage tile 0
    copyW(0, 0);
    prodZ(0, 0);
    asm volatile("cp.async.wait_group 0;");

    for (int it = 0; it < H; ++it) {
        const int s = it & 1;
        __syncthreads();   // bar_A: everyone done reading stage s^1
        if (it + 1 < H) {
            copyW(it + 1, s ^ 1);
            prodZ(it + 1, s ^ 1);
            asm volatile("cp.async.wait_group 1;");
        } else {
            asm volatile("cp.async.wait_group 0;");
        }
        __syncthreads();   // bar_B: stage s (W+Z) visible to all
        const uint32_t st = sb + STAGE_OFF + s * 65536;
#pragma unroll
        for (int kk = 0; kk < 4; kk++) {
            uint32_t ah[2][4], al[2][4];
#pragma unroll
            for (int mi = 0; mi < 2; mi++) {
                ldsm4(ah[mi], st + aRow[mi] + aCol[kk]);
                ldsm4(al[mi], st + 16384 + aRow[mi] + aCol[kk]);
            }
#pragma unroll
            for (int p = 0; p < 4; p++) {
                uint32_t bh[4], bl[4];
                ldsm4(bh, st + 32768 + bRow[p] + bCol[kk]);
                ldsm4(bl, st + 49152 + bRow[p] + bCol[kk]);
#pragma unroll
                for (int mi = 0; mi < 2; mi++) {
#pragma unroll
                    for (int q = 0; q < 2; q++) {
                        float* c = C[mi][2 * p + q];
                        mma_bf16(c, ah[mi], bh[2 * q], bh[2 * q + 1]);
                        mma_bf16(c, ah[mi], bl[2 * q], bl[2 * q + 1]);
                        mma_bf16(c, al[mi], bh[2 * q], bh[2 * q + 1]);
                    }
                }
            }
        }
    }

    // Epilogue: bias + relu, write x_next, reduce over d -> out
    const int mrow = lane >> 2;
    const int qn   = lane & 3;
#pragma unroll
    for (int mi = 0; mi < 2; mi++) {
#pragma unroll
        for (int h2 = 0; h2 < 2; h2++) {
            const int o = 32 * wm + 16 * mi + 8 * h2 + mrow;
            const float bv = __ldg(bias + o);
#pragma unroll
            for (int bl2 = 0; bl2 < 2; bl2++) {
                const int b = b0 + 2 * wn + bl2;
                float sum = 0.f;
#pragma unroll
                for (int jj = 0; jj < 4; jj++) {
                    const int j = 4 * bl2 + jj;
                    float v0 = fmaxf(C[mi][j][2 * h2]     + bv, 0.f);
                    float v1 = fmaxf(C[mi][j][2 * h2 + 1] + bv, 0.f);
                    sum += v0 + v1;
                    if (WRITE_NEXT) {
                        const int d = 8 * jj + 2 * qn;
                        *(float2*)(x_next + ((size_t)b * 128 + o) * 32 + d) =
                            make_float2(v0, v1);
                    }
                }
                sum += __shfl_xor_sync(0xffffffffu, sum, 1);
                sum += __shfl_xor_sync(0xffffffffu, sum, 2);
                if (qn == 0) out[(size_t)b * 384 + out_off + o] = sum;
            }
        }
    }
}

// ---------------------------------------------------------------------------
extern "C" void kernel_launch(void* const* d_in, const int* in_sizes, int n_in,
                              void* d_out, int out_size)
{
    (void)in_sizes; (void)n_in; (void)out_size;
    const float* input = (const float*)d_in[0];
    const float* W0    = (const float*)d_in[1];
    const float* b0    = (const float*)d_in[2];
    const float* W1    = (const float*)d_in[3];
    const float* b1    = (const float*)d_in[4];
    const float* W2    = (const float*)d_in[5];
    const float* b2    = (const float*)d_in[6];
    float* out = (float*)d_out;

    float *x1, *x2; uint4 *w0p, *w1p, *w2p;
    cudaGetSymbolAddress((void**)&x1, g_x1);
    cudaGetSymbolAddress((void**)&x2, g_x2);
    cudaGetSymbolAddress((void**)&w0p, g_W0);
    cudaGetSymbolAddress((void**)&w1p, g_W1);
    cudaGetSymbolAddress((void**)&w2p, g_W2);

    cudaFuncSetAttribute(layer_mma<64,  true >, cudaFuncAttributeMaxDynamicSharedMemorySize, SMEM_TOTAL);
    cudaFuncSetAttribute(layer_mma<128, true >, cudaFuncAttributeMaxDynamicSharedMemorySize, SMEM_TOTAL);
    cudaFuncSetAttribute(layer_mma<128, false>, cudaFuncAttributeMaxDynamicSharedMemorySize, SMEM_TOTAL);

    prep_w<<<256, 256>>>(W0, w0p, 4096);
    prep_w<<<512, 256>>>(W1, w1p, 8192);
    prep_w<<<512, 256>>>(W2, w2p, 8192);

    dim3 grid(128), block(256);
    layer_mma<64,  true ><<<grid, block, SMEM_TOTAL>>>(input, input, w0p, b0, x1, out, 0);
    layer_mma<128, true ><<<grid, block, SMEM_TOTAL>>>(x1,    input, w1p, b1, x2, out, 128);
    layer_mma<128, false><<<grid, block, SMEM_TOTAL>>>(x2,    input, w2p, b2, nullptr, out, 256);
}

// round 5
// speedup vs baseline: 3.7651x; 1.0981x over previous
#include <cuda_runtime.h>
#include <cuda_bf16.h>
#include <cstdint>
#include <cstddef>

// ---------------------------------------------------------------------------
// pre[b,o,d] = sum_{h,f} W[o, h*64+f] * x[b,h,d] * inp[b,f,d] + bias[o]
// x_next = relu(pre);  out[:, off+o] = sum_d relu(pre);  3 chained layers.
// B=512, F=64, D=32, O=128.
//
// GEMM per layer: D[o=128, n=(b*32+d)=16384] = W[o,k] * Z[k,n],
// Z generated on the fly in SMEM. mma.sync m16n8k16 bf16, 3-MMA split
// (Whi*Zhi + Whi*Zlo + Wlo*Zhi). W pre-split once into swizzled tiles.
// CTA: M=128, N=128 (4 batches), K-tile 64, double buffer.
//
// Round-5: single barrier per tile + SMSP-staggered produce/MMA phases so the
// tensor pipe stays fed while Z for the next tile is being produced.
// ---------------------------------------------------------------------------

#define SW128(o) ((o) ^ (((o) >> 3) & 0x70))

__device__ __align__(16) float g_x1[512 * 128 * 32];
__device__ __align__(16) float g_x2[512 * 128 * 32];
__device__ uint4 g_W0[128 * 4096 * 4 / 16];
__device__ uint4 g_W1[128 * 8192 * 4 / 16];
__device__ uint4 g_W2[128 * 8192 * 4 / 16];

__device__ __forceinline__ uint32_t smem_u32(const void* p) {
    uint32_t a;
    asm("{ .reg .u64 t; cvta.to.shared.u64 t, %1; cvt.u32.u64 %0, t; }"
        : "=r"(a) : "l"(p));
    return a;
}

__device__ __forceinline__ void split2(float z0, float z1,
                                       uint32_t& hi, uint32_t& lo) {
    __nv_bfloat162 h = __floats2bfloat162_rn(z0, z1);
    float2 hf = __bfloat1622float2(h);
    __nv_bfloat162 l = __floats2bfloat162_rn(z0 - hf.x, z1 - hf.y);
    hi = reinterpret_cast<uint32_t&>(h);
    lo = reinterpret_cast<uint32_t&>(l);
}

__device__ __forceinline__ void ldsm4(uint32_t r[4], uint32_t addr) {
    asm volatile("ldmatrix.sync.aligned.m8n8.x4.shared.b16 {%0,%1,%2,%3}, [%4];"
                 : "=r"(r[0]), "=r"(r[1]), "=r"(r[2]), "=r"(r[3]) : "r"(addr));
}

__device__ __forceinline__ void mma_bf16(float c[4], const uint32_t a[4],
                                         uint32_t b0, uint32_t b1) {
    asm volatile(
        "mma.sync.aligned.m16n8k16.row.col.f32.bf16.bf16.f32 "
        "{%0,%1,%2,%3}, {%4,%5,%6,%7}, {%8,%9}, {%0,%1,%2,%3};"
        : "+f"(c[0]), "+f"(c[1]), "+f"(c[2]), "+f"(c[3])
        : "r"(a[0]), "r"(a[1]), "r"(a[2]), "r"(a[3]), "r"(b0), "r"(b1));
}

// --------------------------- W prep: fp32 -> split bf16 tiles ---------------
__global__ __launch_bounds__(256)
void prep_w(const float* __restrict__ W, uint4* __restrict__ dst, int K) {
    int idx = blockIdx.x * 256 + threadIdx.x;
    int cpr = K >> 3;
    if (idx >= 128 * cpr) return;
    int o = idx / cpr;
    int k = (idx % cpr) * 8;
    const float4* src = (const float4*)(W + (size_t)o * K + k);
    float4 v0 = src[0], v1 = src[1];
    float zf[8] = {v0.x, v0.y, v0.z, v0.w, v1.x, v1.y, v1.z, v1.w};
    uint32_t hi[4], lo[4];
#pragma unroll
    for (int p = 0; p < 4; p++) split2(zf[2 * p], zf[2 * p + 1], hi[p], lo[p]);
    char* base = (char*)dst + (size_t)(k >> 6) * 32768;
    uint32_t off = SW128((uint32_t)(o * 128 + (k & 63) * 2));
    *(uint4*)(base + off)         = make_uint4(hi[0], hi[1], hi[2], hi[3]);
    *(uint4*)(base + 16384 + off) = make_uint4(lo[0], lo[1], lo[2], lo[3]);
}

// --------------------------- main layer kernel ------------------------------
// SMEM: [0,32768) inp_s; [32768 + s*65536): Whi(16K) Wlo(16K) Zhi(16K) Zlo(16K)
#define SMEM_TOTAL 163840
#define STAGE_OFF  32768

template <int H, bool WRITE_NEXT>
__global__ __launch_bounds__(256, 1)
void layer_mma(const float* __restrict__ x,
               const float* __restrict__ inp,
               const uint4* __restrict__ Wsp,
               const float* __restrict__ bias,
               float* __restrict__ x_next,
               float* __restrict__ out,
               int out_off)
{
    extern __shared__ char smem[];
    const uint32_t sb = smem_u32(smem);
    float* inp_s = (float*)smem;
    const int tid  = threadIdx.x;
    const int lane = tid & 31;
    const int w    = tid >> 5;
    const int wm   = w & 3;
    const int wn   = w >> 2;
    const int b0   = blockIdx.x * 4;

    {
        const float4* src = (const float4*)(inp + (size_t)b0 * 2048);
        float4* dst = (float4*)inp_s;
#pragma unroll
        for (int i = 0; i < 8; i++) dst[tid + i * 256] = src[tid + i * 256];
    }

    // Producer constants
    const int n  = tid & 127;
    const int bq = n >> 5;
    const int dd = n & 31;
    const int kh = (tid >> 7) * 32;
    const float* xp = x + ((size_t)(b0 + bq) * H) * 32 + dd;
    const float* ip = inp_s + (size_t)bq * 2048 + kh * 32 + dd;
    const uint32_t zrow  = (uint32_t)n * 128;
    const uint32_t zmask = (uint32_t)((n & 7) << 4);
    const uint32_t zcol0 = (uint32_t)(kh * 2);

    // MMA constants: linear row bases + swizzled per-kk column offsets
    const int g = lane >> 3;
    const uint32_t maskL = (uint32_t)((lane & 7) << 4);
    uint32_t aRow[2], bRow[4], aCol[4], bCol[4];
#pragma unroll
    for (int mi = 0; mi < 2; mi++)
        aRow[mi] = (uint32_t)((32 * wm + 16 * mi + (lane & 7) + (g & 1) * 8) * 128);
#pragma unroll
    for (int p = 0; p < 4; p++)
        bRow[p] = (uint32_t)((64 * wn + 16 * p + 8 * ((g >> 1) & 1) + (lane & 7)) * 128);
#pragma unroll
    for (int kk = 0; kk < 4; kk++) {
        aCol[kk] = ((uint32_t)(((g >> 1) & 1) * 16 + 32 * kk)) ^ maskL;
        bCol[kk] = ((uint32_t)((g & 1) * 16 + 32 * kk)) ^ maskL;
    }

    float C[2][8][4];
#pragma unroll
    for (int i = 0; i < 2; i++)
#pragma unroll
        for (int j = 0; j < 8; j++)
#pragma unroll
            for (int q = 0; q < 4; q++) C[i][j][q] = 0.f;

    const char* gW = (const char*)Wsp;

    auto prodZ = [&](int h, int s) {
        char* zp = smem + STAGE_OFF + s * 65536 + 32768;
        const float xv = __ldg(xp + h * 32);
#pragma unroll
        for (int i = 0; i < 4; i++) {
            float z[8];
#pragma unroll
            for (int j = 0; j < 8; j++) z[j] = xv * ip[(i * 8 + j) * 32];
            uint32_t hi[4], lo[4];
#pragma unroll
            for (int p = 0; p < 4; p++)
                split2(z[2 * p], z[2 * p + 1], hi[p], lo[p]);
            uint32_t off = zrow + ((zcol0 + 16u * i) ^ zmask);
            *(uint4*)(zp + off)         = make_uint4(hi[0], hi[1], hi[2], hi[3]);
            *(uint4*)(zp + 16384 + off) = make_uint4(lo[0], lo[1], lo[2], lo[3]);
        }
    };
    auto copyW = [&](int it, int s) {
        uint32_t dsb = sb + STAGE_OFF + s * 65536 + tid * 16;
        const char* srcW = gW + (size_t)it * 32768 + tid * 16;
#pragma unroll
        for (int i = 0; i < 8; i++)
            asm volatile("cp.async.cg.shared.global [%0], [%1], 16;"
                         :: "r"(dsb + i * 4096), "l"(srcW + i * 4096));
        asm volatile("cp.async.commit_group;");
    };
    auto doMMA = [&](int s) {
        const uint32_t st = sb + STAGE_OFF + s * 65536;
#pragma unroll
        for (int kk = 0; kk < 4; kk++) {
            uint32_t ah[2][4], al[2][4];
#pragma unroll
            for (int mi = 0; mi < 2; mi++) {
                ldsm4(ah[mi], st + aRow[mi] + aCol[kk]);
                ldsm4(al[mi], st + 16384 + aRow[mi] + aCol[kk]);
            }
#pragma unroll
            for (int p = 0; p < 4; p++) {
                uint32_t bh[4], bl[4];
                ldsm4(bh, st + 32768 + bRow[p] + bCol[kk]);
                ldsm4(bl, st + 49152 + bRow[p] + bCol[kk]);
#pragma unroll
                for (int mi = 0; mi < 2; mi++) {
#pragma unroll
                    for (int q = 0; q < 2; q++) {
                        float* c = C[mi][2 * p + q];
                        mma_bf16(c, ah[mi], bh[2 * q], bh[2 * q + 1]);
                        mma_bf16(c, ah[mi], bl[2 * q], bl[2 * q + 1]);
                        mma_bf16(c, al[mi], bh[2 * q], bh[2 * q + 1]);
                    }
                }
            }
        }
    };

    __syncthreads();   // inp_s ready

    // Prologue: stage tile 0
    copyW(0, 0);
    prodZ(0, 0);

    // One barrier per tile. Produce(s^1) overlaps MMA(s): disjoint stages.
    // Warps 0-3 produce first, warps 4-7 MMA first (one of each per SMSP),
    // so the tensor unit on every SMSP is fed during the produce phase.
    for (int it = 0; it < H; ++it) {
        const int s = it & 1;
        __syncthreads();   // stage s fully produced; stage s^1 fully consumed
        if (w & 4) {
            // MMA-first: W(s) group is the only pending one before this commit
            if (it + 1 < H) copyW(it + 1, s ^ 1);
            if (it + 1 < H) { asm volatile("cp.async.wait_group 1;"); }
            else            { asm volatile("cp.async.wait_group 0;"); }
            doMMA(s);
            if (it + 1 < H) prodZ(it + 1, s ^ 1);
        } else {
            if (it + 1 < H) { copyW(it + 1, s ^ 1); prodZ(it + 1, s ^ 1); }
            if (it + 1 < H) { asm volatile("cp.async.wait_group 1;"); }
            else            { asm volatile("cp.async.wait_group 0;"); }
            doMMA(s);
        }
    }

    // Epilogue: bias + relu, write x_next, reduce over d -> out
    const int mrow = lane >> 2;
    const int qn   = lane & 3;
#pragma unroll
    for (int mi = 0; mi < 2; mi++) {
#pragma unroll
        for (int h2 = 0; h2 < 2; h2++) {
            const int o = 32 * wm + 16 * mi + 8 * h2 + mrow;
            const float bv = __ldg(bias + o);
#pragma unroll
            for (int bl2 = 0; bl2 < 2; bl2++) {
                const int b = b0 + 2 * wn + bl2;
                float sum = 0.f;
#pragma unroll
                for (int jj = 0; jj < 4; jj++) {
                    const int j = 4 * bl2 + jj;
                    float v0 = fmaxf(C[mi][j][2 * h2]     + bv, 0.f);
                    float v1 = fmaxf(C[mi][j][2 * h2 + 1] + bv, 0.f);
                    sum += v0 + v1;
                    if (WRITE_NEXT) {
                        const int d = 8 * jj + 2 * qn;
                        *(float2*)(x_next + ((size_t)b * 128 + o) * 32 + d) =
                            make_float2(v0, v1);
                    }
                }
                sum += __shfl_xor_sync(0xffffffffu, sum, 1);
                sum += __shfl_xor_sync(0xffffffffu, sum, 2);
                if (qn == 0) out[(size_t)b * 384 + out_off + o] = sum;
            }
        }
    }
}

// ---------------------------------------------------------------------------
extern "C" void kernel_launch(void* const* d_in, const int* in_sizes, int n_in,
                              void* d_out, int out_size)
{
    (void)in_sizes; (void)n_in; (void)out_size;
    const float* input = (const float*)d_in[0];
    const float* W0    = (const float*)d_in[1];
    const float* b0    = (const float*)d_in[2];
    const float* W1    = (const float*)d_in[3];
    const float* b1    = (const float*)d_in[4];
    const float* W2    = (const float*)d_in[5];
    const float* b2    = (const float*)d_in[6];
    float* out = (float*)d_out;

    float *x1, *x2; uint4 *w0p, *w1p, *w2p;
    cudaGetSymbolAddress((void**)&x1, g_x1);
    cudaGetSymbolAddress((void**)&x2, g_x2);
    cudaGetSymbolAddress((void**)&w0p, g_W0);
    cudaGetSymbolAddress((void**)&w1p, g_W1);
    cudaGetSymbolAddress((void**)&w2p, g_W2);

    cudaFuncSetAttribute(layer_mma<64,  true >, cudaFuncAttributeMaxDynamicSharedMemorySize, SMEM_TOTAL);
    cudaFuncSetAttribute(layer_mma<128, true >, cudaFuncAttributeMaxDynamicSharedMemorySize, SMEM_TOTAL);
    cudaFuncSetAttribute(layer_mma<128, false>, cudaFuncAttributeMaxDynamicSharedMemorySize, SMEM_TOTAL);

    prep_w<<<256, 256>>>(W0, w0p, 4096);
    prep_w<<<512, 256>>>(W1, w1p, 8192);
    prep_w<<<512, 256>>>(W2, w2p, 8192);

    dim3 grid(128), block(256);
    layer_mma<64,  true ><<<grid, block, SMEM_TOTAL>>>(input, input, w0p, b0, x1, out, 0);
    layer_mma<128, true ><<<grid, block, SMEM_TOTAL>>>(x1,    input, w1p, b1, x2, out, 128);
    layer_mma<128, false><<<grid, block, SMEM_TOTAL>>>(x2,    input, w2p, b2, nullptr, out, 256);
}